// round 9
// baseline (speedup 1.0000x reference)
#include <cuda_runtime.h>
#include <cuda_bf16.h>
#include <stdint.h>

// ScaledDotProductAttention: B=2, H=16, S=2048, D=64, scale=8
#define BB 2
#define HH 16
#define SS 2048
#define DD 64
#define QB 64             // q rows per CTA
#define NC 128            // k cols per chunk
#define NCHUNK (SS / NC)  // 16
#define NTHR 256          // 8 warps: 2 q-groups (m32) x 4 k-groups (n32)
#define NELEM (BB * HH * SS * DD)

#define STRB 144                  // smem row stride bytes
#define QTILEB (64 * STRB)        // 9216
#define KTILEB (128 * STRB)       // 18432

#define OFF_QH 0
#define OFF_QL QTILEB
#define OFF_STAGE (2 * QTILEB)                       // K tiles: st{0,1} x {H,L}
#define KH_OFF(st) (OFF_STAGE + ((st) * 2 + 0) * KTILEB)
#define KL_OFF(st) (OFF_STAGE + ((st) * 2 + 1) * KTILEB)
#define OFF_V (OFF_STAGE + 4 * KTILEB)               // V tiles: st{0,1} x {H,L}
#define VH_OFF(st) (OFF_V + ((st) * 2 + 0) * KTILEB)
#define VL_OFF(st) (OFF_V + ((st) * 2 + 1) * KTILEB)
#define OFF_MSK (OFF_V + 4 * KTILEB)                 // int[2048]
#define OFF_L4  (OFF_MSK + SS * 4)                   // float[64][4]
#define SMEM_TOTAL (OFF_L4 + 64 * 4 * 4)             // 175104 B

// pre-converted bf16 hi/lo tensors (Q pre-scaled by 1/8)
__device__ __nv_bfloat16 g_qh[NELEM], g_ql[NELEM];
__device__ __nv_bfloat16 g_kh[NELEM], g_kl[NELEM];
__device__ __nv_bfloat16 g_vh[NELEM], g_vl[NELEM];

__device__ __forceinline__ uint32_t s2u(const void* p) {
    uint32_t a;
    asm("{ .reg .u64 t; cvta.to.shared.u64 t, %1; cvt.u32.u64 %0, t; }" : "=r"(a) : "l"(p));
    return a;
}
__device__ __forceinline__ void ldsm4(uint32_t r[4], uint32_t a) {
    asm volatile("ldmatrix.sync.aligned.m8n8.x4.shared.b16 {%0,%1,%2,%3}, [%4];"
                 : "=r"(r[0]), "=r"(r[1]), "=r"(r[2]), "=r"(r[3]) : "r"(a));
}
__device__ __forceinline__ void ldsm4t(uint32_t r[4], uint32_t a) {
    asm volatile("ldmatrix.sync.aligned.m8n8.x4.trans.shared.b16 {%0,%1,%2,%3}, [%4];"
                 : "=r"(r[0]), "=r"(r[1]), "=r"(r[2]), "=r"(r[3]) : "r"(a));
}
__device__ __forceinline__ void mmab(float c[4], const uint32_t a[4], uint32_t b0, uint32_t b1) {
    asm volatile("mma.sync.aligned.m16n8k16.row.col.f32.bf16.bf16.f32 "
                 "{%0,%1,%2,%3}, {%4,%5,%6,%7}, {%8,%9}, {%0,%1,%2,%3};"
                 : "+f"(c[0]), "+f"(c[1]), "+f"(c[2]), "+f"(c[3])
                 : "r"(a[0]), "r"(a[1]), "r"(a[2]), "r"(a[3]), "r"(b0), "r"(b1));
}
__device__ __forceinline__ uint32_t pkbf(__nv_bfloat16 a, __nv_bfloat16 b) {
    __nv_bfloat162 t(a, b);
    return *(uint32_t*)&t;
}
#define CPA16(dst, src) \
    asm volatile("cp.async.cg.shared.global [%0], [%1], 16;" :: "r"(dst), "l"(src) : "memory")
#define CPA_COMMIT() asm volatile("cp.async.commit_group;" ::: "memory")
#define CPA_WAIT0()  asm volatile("cp.async.wait_group 0;" ::: "memory")

// ---- pre-pass: fp32 -> bf16 hi/lo split ----
__device__ __forceinline__ void split4(float4 x, uint2& hi, uint2& lo) {
    __nv_bfloat16 h0 = __float2bfloat16(x.x), h1 = __float2bfloat16(x.y);
    __nv_bfloat16 h2 = __float2bfloat16(x.z), h3 = __float2bfloat16(x.w);
    hi = make_uint2(pkbf(h0, h1), pkbf(h2, h3));
    lo = make_uint2(pkbf(__float2bfloat16(x.x - __bfloat162float(h0)),
                         __float2bfloat16(x.y - __bfloat162float(h1))),
                    pkbf(__float2bfloat16(x.z - __bfloat162float(h2)),
                         __float2bfloat16(x.w - __bfloat162float(h3))));
}
__global__ void convert_kernel(const float* __restrict__ Q, const float* __restrict__ K,
                               const float* __restrict__ V)
{
    long i = (long)blockIdx.x * blockDim.x + threadIdx.x;
    if (i >= NELEM / 4) return;
    long e = i * 4;
    uint2 hi, lo;
    float4 q = *(const float4*)&Q[e];
    q.x *= 0.125f; q.y *= 0.125f; q.z *= 0.125f; q.w *= 0.125f;
    split4(q, hi, lo);
    *(uint2*)&g_qh[e] = hi; *(uint2*)&g_ql[e] = lo;
    split4(*(const float4*)&K[e], hi, lo);
    *(uint2*)&g_kh[e] = hi; *(uint2*)&g_kl[e] = lo;
    split4(*(const float4*)&V[e], hi, lo);
    *(uint2*)&g_vh[e] = hi; *(uint2*)&g_vl[e] = lo;
}

// cp.async tiles (gmem row-major [rows x 64] bf16) into stride-144 smem
__device__ __forceinline__ void cpa_tile128(uint32_t dstbase, const __nv_bfloat16* src, int tid) {
    #pragma unroll
    for (int i = tid; i < 1024; i += NTHR) {
        int r = i >> 3, c8 = i & 7;
        CPA16(dstbase + r * STRB + c8 * 16, src + (long)r * DD + c8 * 8);
    }
}
__device__ __forceinline__ void cpa_tile64(uint32_t dstbase, const __nv_bfloat16* src, int tid) {
    #pragma unroll
    for (int i = tid; i < 512; i += NTHR) {
        int r = i >> 3, c8 = i & 7;
        CPA16(dstbase + r * STRB + c8 * 16, src + (long)r * DD + c8 * 8);
    }
}

// S = Q·K^T for this warp's m32 x n32 slice (Q frags in regs), 3-term bf16
__device__ __forceinline__ void compute_S32(float acc[2][4][4],
                                            const uint32_t aH[2][4][4],
                                            const uint32_t aL[2][4][4],
                                            uint32_t khB, uint32_t klB)
{
    #pragma unroll
    for (int t = 0; t < 2; t++)
        #pragma unroll
        for (int j = 0; j < 4; j++)
            #pragma unroll
            for (int i = 0; i < 4; i++) acc[t][j][i] = 0.0f;
    #pragma unroll
    for (int s = 0; s < 4; s++) {
        #pragma unroll
        for (int jp = 0; jp < 2; jp++) {
            uint32_t bH[4], bL[4];
            ldsm4(bH, khB + jp * (16 * STRB) + s * 32);
            ldsm4(bL, klB + jp * (16 * STRB) + s * 32);
            #pragma unroll
            for (int t = 0; t < 2; t++) {
                mmab(acc[t][2 * jp],     aH[t][s], bH[0], bH[1]);
                mmab(acc[t][2 * jp + 1], aH[t][s], bH[2], bH[3]);
                mmab(acc[t][2 * jp],     aH[t][s], bL[0], bL[1]);
                mmab(acc[t][2 * jp + 1], aH[t][s], bL[2], bL[3]);
                mmab(acc[t][2 * jp],     aL[t][s], bH[0], bH[1]);
                mmab(acc[t][2 * jp + 1], aL[t][s], bH[2], bH[3]);
            }
        }
    }
}

__global__ __launch_bounds__(NTHR, 1)
void fa_mma_kernel(const int* __restrict__ mask,
                   float* __restrict__ out_o, float* __restrict__ out_p)
{
    extern __shared__ char sm[];
    const uint32_t sb = s2u(sm);
    const int tid = threadIdx.x, wid = tid >> 5, lane = tid & 31;
    const int qg = wid >> 2, kg = wid & 3;
    const int q0 = qg * 32;

    const int qtile = blockIdx.x, h = blockIdx.y, b = blockIdx.z;
    const long bh = (long)(b * HH + h);
    const long qbase = bh * SS + (long)qtile * QB;
    const long kvbase = bh * SS;

    // ---- prologue: Q tiles + mask + chunk 0 ----
    cpa_tile64(sb + OFF_QH, g_qh + qbase * DD, tid);
    cpa_tile64(sb + OFF_QL, g_ql + qbase * DD, tid);
    #pragma unroll
    for (int i = tid; i < 512; i += NTHR)
        CPA16(sb + OFF_MSK + i * 16, mask + (long)b * SS + i * 4);
    cpa_tile128(sb + KH_OFF(0), g_kh + kvbase * DD, tid);
    cpa_tile128(sb + KL_OFF(0), g_kl + kvbase * DD, tid);
    cpa_tile128(sb + VH_OFF(0), g_vh + kvbase * DD, tid);
    cpa_tile128(sb + VL_OFF(0), g_vl + kvbase * DD, tid);
    CPA_COMMIT();

    // per-lane ldmatrix addresses
    const uint32_t aoff = (uint32_t)(q0 + (lane & 15)) * STRB + ((lane >> 4) & 1) * 16;
    const uint32_t koff = (uint32_t)(kg * 32 + (lane & 7) + ((lane & 16) ? 8 : 0)) * STRB
                        + ((lane & 8) ? 16 : 0);
    const uint32_t voff = (uint32_t)(kg * 32 + (lane & 15)) * STRB + ((lane >> 4) & 1) * 16;

    int* msk = (int*)(sm + OFF_MSK);

    CPA_WAIT0();
    __syncthreads();

    // ---- hoist Q fragments: m32 x k64, hi+lo (64 regs) ----
    uint32_t aH[2][4][4], aL[2][4][4];
    #pragma unroll
    for (int t = 0; t < 2; t++)
        #pragma unroll
        for (int s = 0; s < 4; s++) {
            ldsm4(aH[t][s], sb + OFF_QH + aoff + t * (16 * STRB) + s * 32);
            ldsm4(aL[t][s], sb + OFF_QL + aoff + t * (16 * STRB) + s * 32);
        }

    float oacc[2][8][4];
    #pragma unroll
    for (int t = 0; t < 2; t++)
        #pragma unroll
        for (int j = 0; j < 8; j++)
            #pragma unroll
            for (int i = 0; i < 4; i++) oacc[t][j][i] = 0.0f;
    float rs[2][2] = {{0.f, 0.f}, {0.f, 0.f}};

    // ================= Pass 1 =================
    for (int ch = 0; ch < NCHUNK; ch++) {
        const int st = ch & 1;
        if (ch > 0) { CPA_WAIT0(); __syncthreads(); }
        if (ch + 1 < NCHUNK) {
            const long nb = (kvbase + (long)(ch + 1) * NC) * DD;
            const int ns = st ^ 1;
            cpa_tile128(sb + KH_OFF(ns), g_kh + nb, tid);
            cpa_tile128(sb + KL_OFF(ns), g_kl + nb, tid);
            cpa_tile128(sb + VH_OFF(ns), g_vh + nb, tid);
            cpa_tile128(sb + VL_OFF(ns), g_vl + nb, tid);
            CPA_COMMIT();
        }

        float acc[2][4][4];
        compute_S32(acc, aH, aL, sb + KH_OFF(st) + koff, sb + KL_OFF(st) + koff);

        // fused epilogue + PV per k16 step s2 (warp's k32 -> 2 steps)
        #pragma unroll
        for (int s2 = 0; s2 < 2; s2++) {
            uint32_t PH[2][4], PL[2][4];
            #pragma unroll
            for (int t = 0; t < 2; t++)
                #pragma unroll
                for (int hf = 0; hf < 2; hf++) {
                    const int jt = 2 * s2 + hf;
                    int colb = ch * NC + kg * 32 + 8 * jt + 2 * (lane & 3);
                    int2 mm = *(const int2*)&msk[colb];
                    float m0 = mm.x ? 1.0f : 0.0f, m1 = mm.y ? 1.0f : 0.0f;
                    float e0 = __expf(acc[t][jt][0]) * m0, e1 = __expf(acc[t][jt][1]) * m1;
                    float e2 = __expf(acc[t][jt][2]) * m0, e3 = __expf(acc[t][jt][3]) * m1;
                    rs[t][0] += e0 + e1; rs[t][1] += e2 + e3;
                    __nv_bfloat16 h0 = __float2bfloat16(e0), h1 = __float2bfloat16(e1);
                    __nv_bfloat16 h2 = __float2bfloat16(e2), h3 = __float2bfloat16(e3);
                    float l0 = e0 - __bfloat162float(h0), l1 = e1 - __bfloat162float(h1);
                    float l2 = e2 - __bfloat162float(h2), l3 = e3 - __bfloat162float(h3);
                    PH[t][2 * hf]     = pkbf(h0, h1);
                    PH[t][2 * hf + 1] = pkbf(h2, h3);
                    PL[t][2 * hf]     = pkbf(__float2bfloat16(l0), __float2bfloat16(l1));
                    PL[t][2 * hf + 1] = pkbf(__float2bfloat16(l2), __float2bfloat16(l3));
                }
            #pragma unroll
            for (int dp = 0; dp < 4; dp++) {
                uint32_t vH[4], vL[4];
                ldsm4t(vH, sb + VH_OFF(st) + voff + s2 * (16 * STRB) + dp * 32);
                ldsm4t(vL, sb + VL_OFF(st) + voff + s2 * (16 * STRB) + dp * 32);
                #pragma unroll
                for (int t = 0; t < 2; t++) {
                    mmab(oacc[t][2 * dp],     PH[t], vH[0], vH[1]);
                    mmab(oacc[t][2 * dp + 1], PH[t], vH[2], vH[3]);
                    mmab(oacc[t][2 * dp],     PH[t], vL[0], vL[1]);
                    mmab(oacc[t][2 * dp + 1], PH[t], vL[2], vL[3]);
                    mmab(oacc[t][2 * dp],     PL[t], vH[0], vH[1]);
                    mmab(oacc[t][2 * dp + 1], PL[t], vH[2], vH[3]);
                }
            }
        }
    }

    __syncthreads();   // pass-1 compute done; stages free

    // prefetch pass-2 chunk 0 (K only) — overlaps rowsum + O reduction
    cpa_tile128(sb + KH_OFF(0), g_kh + kvbase * DD, tid);
    cpa_tile128(sb + KL_OFF(0), g_kl + kvbase * DD, tid);
    CPA_COMMIT();

    // ---- row sums: quad-lane reduce, then 4-way kg sum via smem ----
    const int r0l = lane >> 2, c0 = 2 * (lane & 3);
    #pragma unroll
    for (int t = 0; t < 2; t++)
        #pragma unroll
        for (int i = 0; i < 2; i++) {
            rs[t][i] += __shfl_xor_sync(0xffffffffu, rs[t][i], 1);
            rs[t][i] += __shfl_xor_sync(0xffffffffu, rs[t][i], 2);
        }
    float* l4 = (float*)(sm + OFF_L4);
    if ((lane & 3) == 0) {
        #pragma unroll
        for (int t = 0; t < 2; t++) {
            l4[(q0 + t * 16 + r0l) * 4 + kg]     = rs[t][0];
            l4[(q0 + t * 16 + 8 + r0l) * 4 + kg] = rs[t][1];
        }
    }
    // ---- O partial store (kg>0) into free V region ----
    float* stg = (float*)(sm + OFF_V);   // 6 regions x 2048 floats
    if (kg > 0) {
        float* rg = stg + (qg * 3 + kg - 1) * 2048;
        #pragma unroll
        for (int t = 0; t < 2; t++)
            #pragma unroll
            for (int nt = 0; nt < 8; nt++) {
                int row = t * 16 + r0l;
                *(float2*)&rg[row * 64 + 8 * nt + c0] =
                    make_float2(oacc[t][nt][0], oacc[t][nt][1]);
                *(float2*)&rg[(row + 8) * 64 + 8 * nt + c0] =
                    make_float2(oacc[t][nt][2], oacc[t][nt][3]);
            }
    }
    __syncthreads();

    float ilv[2][2];
    #pragma unroll
    for (int t = 0; t < 2; t++) {
        int row = q0 + t * 16 + r0l;
        ilv[t][0] = 1.0f / (l4[row * 4] + l4[row * 4 + 1] + l4[row * 4 + 2] + l4[row * 4 + 3]);
        ilv[t][1] = 1.0f / (l4[(row + 8) * 4] + l4[(row + 8) * 4 + 1]
                          + l4[(row + 8) * 4 + 2] + l4[(row + 8) * 4 + 3]);
    }

    if (kg == 0) {
        #pragma unroll
        for (int j = 0; j < 3; j++) {
            float* rg = stg + (qg * 3 + j) * 2048;
            #pragma unroll
            for (int t = 0; t < 2; t++)
                #pragma unroll
                for (int nt = 0; nt < 8; nt++) {
                    int row = t * 16 + r0l;
                    float2 a = *(const float2*)&rg[row * 64 + 8 * nt + c0];
                    float2 bv = *(const float2*)&rg[(row + 8) * 64 + 8 * nt + c0];
                    oacc[t][nt][0] += a.x;  oacc[t][nt][1] += a.y;
                    oacc[t][nt][2] += bv.x; oacc[t][nt][3] += bv.y;
                }
        }
        #pragma unroll
        for (int t = 0; t < 2; t++) {
            const long row0 = qbase + q0 + t * 16 + r0l;
            #pragma unroll
            for (int nt = 0; nt < 8; nt++) {
                *(float2*)&out_o[row0 * DD + 8 * nt + c0] =
                    make_float2(oacc[t][nt][0] * ilv[t][0], oacc[t][nt][1] * ilv[t][0]);
                *(float2*)&out_o[(row0 + 8) * DD + 8 * nt + c0] =
                    make_float2(oacc[t][nt][2] * ilv[t][1], oacc[t][nt][3] * ilv[t][1]);
            }
        }
    }

    // ================= Pass 2: recompute S, write normalized probs =================
    for (int ch = 0; ch < NCHUNK; ch++) {
        const int st = ch & 1;
        CPA_WAIT0();
        __syncthreads();
        if (ch + 1 < NCHUNK) {
            const long nb = (kvbase + (long)(ch + 1) * NC) * DD;
            const int ns = st ^ 1;
            cpa_tile128(sb + KH_OFF(ns), g_kh + nb, tid);
            cpa_tile128(sb + KL_OFF(ns), g_kl + nb, tid);
            CPA_COMMIT();
        }

        float acc[2][4][4];
        compute_S32(acc, aH, aL, sb + KH_OFF(st) + koff, sb + KL_OFF(st) + koff);

        #pragma unroll
        for (int t = 0; t < 2; t++) {
            const long row0 = qbase + q0 + t * 16 + r0l;
            #pragma unroll
            for (int jt = 0; jt < 4; jt++) {
                int colb = ch * NC + kg * 32 + 8 * jt + 2 * (lane & 3);
                int2 mm = *(const int2*)&msk[colb];
                float m0 = mm.x ? ilv[t][0] : 0.0f, m1 = mm.y ? ilv[t][0] : 0.0f;
                float n0 = mm.x ? ilv[t][1] : 0.0f, n1 = mm.y ? ilv[t][1] : 0.0f;
                *(float2*)&out_p[row0 * SS + colb] =
                    make_float2(__expf(acc[t][jt][0]) * m0, __expf(acc[t][jt][1]) * m1);
                *(float2*)&out_p[(row0 + 8) * SS + colb] =
                    make_float2(__expf(acc[t][jt][2]) * n0, __expf(acc[t][jt][3]) * n1);
            }
        }
    }
}

extern "C" void kernel_launch(void* const* d_in, const int* in_sizes, int n_in,
                              void* d_out, int out_size)
{
    const float* Q    = (const float*)d_in[0];
    const float* K    = (const float*)d_in[1];
    const float* V    = (const float*)d_in[2];
    const int*   mask = (const int*)d_in[3];

    float* out_o = (float*)d_out;                       // [B,H,S,D]
    float* out_p = out_o + (size_t)BB * HH * SS * DD;   // [B,H,S,S]

    convert_kernel<<<NELEM / 4 / 256, 256>>>(Q, K, V);

    cudaFuncSetAttribute(fa_mma_kernel,
                         cudaFuncAttributeMaxDynamicSharedMemorySize, SMEM_TOTAL);
    dim3 grid(SS / QB, HH, BB);   // (32, 16, 2) = 1024 CTAs, 1 per SM (fat regs)
    fa_mma_kernel<<<grid, NTHR, SMEM_TOTAL>>>(mask, out_o, out_p);
}

// round 10
// speedup vs baseline: 1.3086x; 1.3086x over previous
#include <cuda_runtime.h>
#include <cuda_bf16.h>
#include <stdint.h>

// ScaledDotProductAttention: B=2, H=16, S=2048, D=64, scale=8
#define BB 2
#define HH 16
#define SS 2048
#define DD 64
#define QB 64             // q rows per CTA
#define NC 64             // k cols per chunk
#define NCHUNK (SS / NC)  // 32
#define NTHR 256          // 8 warps: 4 q-groups x 2 col-halves
#define NELEM (BB * HH * SS * DD)

#define STRB 144                 // smem row stride bytes (72 bf16, ldmatrix conflict-free)
#define TILEB (64 * STRB)        // 9216 B per [64 x 64] bf16 tile
#define TILE_CHUNKS 512          // 16B chunks per tile

#define OFF_QH 0
#define OFF_QL TILEB
#define OFF_STAGE (2 * TILEB)                 // 8 tiles: stage{0,1} x {KH,KL,VH,VL}
#define ST_OFF(st, t) (OFF_STAGE + ((st) * 4 + (t)) * TILEB)
#define OFF_OST (OFF_STAGE + 2 * TILEB)       // O fp32 stage (16KB) over VH0+VL0
#define OFF_MSK (OFF_STAGE + 8 * TILEB)       // int[2048]
#define OFF_L2  (OFF_MSK + SS * 4)            // float[64][2]
#define SMEM_TOTAL (OFF_L2 + 64 * 2 * 4)      // 100864 B -> 2 CTAs/SM

// pre-converted bf16 hi/lo tensors (Q pre-scaled by 1/8)
__device__ __nv_bfloat16 g_qh[NELEM], g_ql[NELEM];
__device__ __nv_bfloat16 g_kh[NELEM], g_kl[NELEM];
__device__ __nv_bfloat16 g_vh[NELEM], g_vl[NELEM];

__device__ __forceinline__ uint32_t s2u(const void* p) {
    uint32_t a;
    asm("{ .reg .u64 t; cvta.to.shared.u64 t, %1; cvt.u32.u64 %0, t; }" : "=r"(a) : "l"(p));
    return a;
}
__device__ __forceinline__ void ldsm4(uint32_t r[4], uint32_t a) {
    asm volatile("ldmatrix.sync.aligned.m8n8.x4.shared.b16 {%0,%1,%2,%3}, [%4];"
                 : "=r"(r[0]), "=r"(r[1]), "=r"(r[2]), "=r"(r[3]) : "r"(a));
}
__device__ __forceinline__ void ldsm4t(uint32_t r[4], uint32_t a) {
    asm volatile("ldmatrix.sync.aligned.m8n8.x4.trans.shared.b16 {%0,%1,%2,%3}, [%4];"
                 : "=r"(r[0]), "=r"(r[1]), "=r"(r[2]), "=r"(r[3]) : "r"(a));
}
__device__ __forceinline__ void mmab(float c[4], const uint32_t a[4], uint32_t b0, uint32_t b1) {
    asm volatile("mma.sync.aligned.m16n8k16.row.col.f32.bf16.bf16.f32 "
                 "{%0,%1,%2,%3}, {%4,%5,%6,%7}, {%8,%9}, {%0,%1,%2,%3};"
                 : "+f"(c[0]), "+f"(c[1]), "+f"(c[2]), "+f"(c[3])
                 : "r"(a[0]), "r"(a[1]), "r"(a[2]), "r"(a[3]), "r"(b0), "r"(b1));
}
__device__ __forceinline__ uint32_t pkbf(__nv_bfloat16 a, __nv_bfloat16 b) {
    __nv_bfloat162 t(a, b);
    return *(uint32_t*)&t;
}
#define CPA16(dst, src) \
    asm volatile("cp.async.cg.shared.global [%0], [%1], 16;" :: "r"(dst), "l"(src) : "memory")
#define CPA_COMMIT() asm volatile("cp.async.commit_group;" ::: "memory")
#define CPA_WAIT0()  asm volatile("cp.async.wait_group 0;" ::: "memory")

// ---- pre-pass: fp32 -> bf16 hi/lo split ----
__device__ __forceinline__ void split4(float4 x, uint2& hi, uint2& lo) {
    __nv_bfloat16 h0 = __float2bfloat16(x.x), h1 = __float2bfloat16(x.y);
    __nv_bfloat16 h2 = __float2bfloat16(x.z), h3 = __float2bfloat16(x.w);
    hi = make_uint2(pkbf(h0, h1), pkbf(h2, h3));
    lo = make_uint2(pkbf(__float2bfloat16(x.x - __bfloat162float(h0)),
                         __float2bfloat16(x.y - __bfloat162float(h1))),
                    pkbf(__float2bfloat16(x.z - __bfloat162float(h2)),
                         __float2bfloat16(x.w - __bfloat162float(h3))));
}
__global__ void convert_kernel(const float* __restrict__ Q, const float* __restrict__ K,
                               const float* __restrict__ V)
{
    long i = (long)blockIdx.x * blockDim.x + threadIdx.x;
    if (i >= NELEM / 4) return;
    long e = i * 4;
    uint2 hi, lo;
    float4 q = *(const float4*)&Q[e];
    q.x *= 0.125f; q.y *= 0.125f; q.z *= 0.125f; q.w *= 0.125f;
    split4(q, hi, lo);
    *(uint2*)&g_qh[e] = hi; *(uint2*)&g_ql[e] = lo;
    split4(*(const float4*)&K[e], hi, lo);
    *(uint2*)&g_kh[e] = hi; *(uint2*)&g_kl[e] = lo;
    split4(*(const float4*)&V[e], hi, lo);
    *(uint2*)&g_vh[e] = hi; *(uint2*)&g_vl[e] = lo;
}

// cp.async a [64 x 64] bf16 tile into stride-144 smem
__device__ __forceinline__ void cpa_tile(uint32_t dstbase, const __nv_bfloat16* src, int tid) {
    #pragma unroll
    for (int i = tid; i < TILE_CHUNKS; i += NTHR) {
        int r = i >> 3, c8 = i & 7;
        CPA16(dstbase + r * STRB + c8 * 16, src + (long)r * DD + c8 * 8);
    }
}

__global__ __launch_bounds__(NTHR, 2)
void fa_mma_kernel(const int* __restrict__ mask,
                   float* __restrict__ out_o, float* __restrict__ out_p)
{
    extern __shared__ char sm[];
    const uint32_t sb = s2u(sm);
    const int tid = threadIdx.x, wid = tid >> 5, lane = tid & 31;
    const int qg = wid & 3, cg = wid >> 2;
    const int q0 = qg * 16;

    const int qtile = blockIdx.x, h = blockIdx.y, b = blockIdx.z;
    const long bh = (long)(b * HH + h);
    const long qbase = bh * SS + (long)qtile * QB;
    const long kvbase = bh * SS;

    // ---- prologue: Q tiles + mask + KH chunk 0 ----
    cpa_tile(sb + OFF_QH, g_qh + qbase * DD, tid);
    cpa_tile(sb + OFF_QL, g_ql + qbase * DD, tid);
    #pragma unroll
    for (int i = tid; i < 512; i += NTHR)
        CPA16(sb + OFF_MSK + i * 16, mask + (long)b * SS + i * 4);
    cpa_tile(sb + ST_OFF(0, 0), g_kh + kvbase * DD, tid);
    CPA_COMMIT();

    const uint32_t kvrow = (uint32_t)cg * 32 * STRB;
    const uint32_t aoff = (uint32_t)(q0 + (lane & 15)) * STRB + ((lane >> 4) & 1) * 16;
    const uint32_t koff = kvrow + (uint32_t)((lane & 7) + ((lane & 16) ? 8 : 0)) * STRB
                        + ((lane & 8) ? 16 : 0);
    const uint32_t voff = kvrow + (uint32_t)(lane & 15) * STRB + ((lane >> 4) & 1) * 16;

    int* msk = (int*)(sm + OFF_MSK);

    CPA_WAIT0();
    __syncthreads();

    // ---- hoist Q fragments (m16 x k64, hi+lo = 32 regs) ----
    uint32_t aHq[4][4], aLq[4][4];
    #pragma unroll
    for (int s = 0; s < 4; s++) {
        ldsm4(aHq[s], sb + OFF_QH + aoff + s * 32);
        ldsm4(aLq[s], sb + OFF_QL + aoff + s * 32);
    }

    // ================= Pass A: 1-term bf16 scores -> row sums only =================
    float rs0 = 0.0f, rs1 = 0.0f;
    for (int ch = 0; ch < NCHUNK; ch++) {
        const int st = ch & 1;
        if (ch > 0) { CPA_WAIT0(); __syncthreads(); }
        if (ch + 1 < NCHUNK) {
            cpa_tile(sb + ST_OFF(st ^ 1, 0),
                     g_kh + (kvbase + (long)(ch + 1) * NC) * DD, tid);
            CPA_COMMIT();
        }

        float acc[4][4];
        #pragma unroll
        for (int j = 0; j < 4; j++)
            #pragma unroll
            for (int i = 0; i < 4; i++) acc[j][i] = 0.0f;
        #pragma unroll
        for (int s = 0; s < 4; s++) {
            #pragma unroll
            for (int jp = 0; jp < 2; jp++) {
                uint32_t bH[4];
                ldsm4(bH, sb + ST_OFF(st, 0) + koff + jp * (16 * STRB) + s * 32);
                mmab(acc[2 * jp],     aHq[s], bH[0], bH[1]);
                mmab(acc[2 * jp + 1], aHq[s], bH[2], bH[3]);
            }
        }
        #pragma unroll
        for (int jt = 0; jt < 4; jt++) {
            int colb = ch * NC + cg * 32 + 8 * jt + 2 * (lane & 3);
            int2 mm = *(const int2*)&msk[colb];
            float m0 = mm.x ? 1.0f : 0.0f, m1 = mm.y ? 1.0f : 0.0f;
            rs0 += __expf(acc[jt][0]) * m0 + __expf(acc[jt][1]) * m1;
            rs1 += __expf(acc[jt][2]) * m0 + __expf(acc[jt][3]) * m1;
        }
    }

    __syncthreads();   // all warps done with A stages

    // prefetch pass-B chunk 0 (all 4 tiles) — overlaps rowsum reduction
    cpa_tile(sb + ST_OFF(0, 0), g_kh + kvbase * DD, tid);
    cpa_tile(sb + ST_OFF(0, 1), g_kl + kvbase * DD, tid);
    cpa_tile(sb + ST_OFF(0, 2), g_vh + kvbase * DD, tid);
    cpa_tile(sb + ST_OFF(0, 3), g_vl + kvbase * DD, tid);
    CPA_COMMIT();

    // ---- row sums: quad-lane reduce, cross-half via smem ----
    rs0 += __shfl_xor_sync(0xffffffffu, rs0, 1);
    rs0 += __shfl_xor_sync(0xffffffffu, rs0, 2);
    rs1 += __shfl_xor_sync(0xffffffffu, rs1, 1);
    rs1 += __shfl_xor_sync(0xffffffffu, rs1, 2);
    float* l2p = (float*)(sm + OFF_L2);
    if ((lane & 3) == 0) {
        l2p[2 * (q0 + (lane >> 2)) + cg]     = rs0;
        l2p[2 * (q0 + 8 + (lane >> 2)) + cg] = rs1;
    }
    __syncthreads();
    const float il0 = 1.0f / (l2p[2 * (q0 + (lane >> 2))] + l2p[2 * (q0 + (lane >> 2)) + 1]);
    const float il1 = 1.0f / (l2p[2 * (q0 + 8 + (lane >> 2))] + l2p[2 * (q0 + 8 + (lane >> 2)) + 1]);
    const long row0 = qbase + q0 + (lane >> 2);

    float oacc[8][4];
    #pragma unroll
    for (int j = 0; j < 8; j++)
        #pragma unroll
        for (int i = 0; i < 4; i++) oacc[j][i] = 0.0f;

    // ========== Pass B: 3-term S -> normalized P -> write probs + PV ==========
    for (int ch = 0; ch < NCHUNK; ch++) {
        const int st = ch & 1;
        CPA_WAIT0();
        __syncthreads();
        if (ch + 1 < NCHUNK) {
            const long nb = (kvbase + (long)(ch + 1) * NC) * DD;
            const int ns = st ^ 1;
            cpa_tile(sb + ST_OFF(ns, 0), g_kh + nb, tid);
            cpa_tile(sb + ST_OFF(ns, 1), g_kl + nb, tid);
            cpa_tile(sb + ST_OFF(ns, 2), g_vh + nb, tid);
            cpa_tile(sb + ST_OFF(ns, 3), g_vl + nb, tid);
            CPA_COMMIT();
        }

        // 3-term S
        float acc[4][4];
        #pragma unroll
        for (int j = 0; j < 4; j++)
            #pragma unroll
            for (int i = 0; i < 4; i++) acc[j][i] = 0.0f;
        #pragma unroll
        for (int s = 0; s < 4; s++) {
            #pragma unroll
            for (int jp = 0; jp < 2; jp++) {
                uint32_t bH[4], bL[4];
                ldsm4(bH, sb + ST_OFF(st, 0) + koff + jp * (16 * STRB) + s * 32);
                ldsm4(bL, sb + ST_OFF(st, 1) + koff + jp * (16 * STRB) + s * 32);
                mmab(acc[2 * jp],     aHq[s], bH[0], bH[1]);
                mmab(acc[2 * jp + 1], aHq[s], bH[2], bH[3]);
                mmab(acc[2 * jp],     aHq[s], bL[0], bL[1]);
                mmab(acc[2 * jp + 1], aHq[s], bL[2], bL[3]);
                mmab(acc[2 * jp],     aLq[s], bH[0], bH[1]);
                mmab(acc[2 * jp + 1], aLq[s], bH[2], bH[3]);
            }
        }

        const uint32_t vh = sb + ST_OFF(st, 2) + voff, vl = sb + ST_OFF(st, 3) + voff;
        #pragma unroll
        for (int s2 = 0; s2 < 2; s2++) {
            uint32_t PH[4], PL[4];
            #pragma unroll
            for (int hf = 0; hf < 2; hf++) {
                const int jt = 2 * s2 + hf;
                int colb = ch * NC + cg * 32 + 8 * jt + 2 * (lane & 3);
                int2 mm = *(const int2*)&msk[colb];
                float e0 = __expf(acc[jt][0]) * (mm.x ? il0 : 0.0f);
                float e1 = __expf(acc[jt][1]) * (mm.y ? il0 : 0.0f);
                float e2 = __expf(acc[jt][2]) * (mm.x ? il1 : 0.0f);
                float e3 = __expf(acc[jt][3]) * (mm.y ? il1 : 0.0f);
                // normalized probs out (fire-and-forget STG)
                *(float2*)&out_p[row0 * SS + colb]       = make_float2(e0, e1);
                *(float2*)&out_p[(row0 + 8) * SS + colb] = make_float2(e2, e3);
                __nv_bfloat16 h0 = __float2bfloat16(e0), h1 = __float2bfloat16(e1);
                __nv_bfloat16 h2 = __float2bfloat16(e2), h3 = __float2bfloat16(e3);
                float l0 = e0 - __bfloat162float(h0), l1 = e1 - __bfloat162float(h1);
                float l2 = e2 - __bfloat162float(h2), l3 = e3 - __bfloat162float(h3);
                PH[2 * hf]     = pkbf(h0, h1);
                PH[2 * hf + 1] = pkbf(h2, h3);
                PL[2 * hf]     = pkbf(__float2bfloat16(l0), __float2bfloat16(l1));
                PL[2 * hf + 1] = pkbf(__float2bfloat16(l2), __float2bfloat16(l3));
            }
            #pragma unroll
            for (int dp = 0; dp < 4; dp++) {
                uint32_t vH[4], vL[4];
                ldsm4t(vH, vh + s2 * (16 * STRB) + dp * 32);
                ldsm4t(vL, vl + s2 * (16 * STRB) + dp * 32);
                mmab(oacc[2 * dp],     PH, vH[0], vH[1]);
                mmab(oacc[2 * dp + 1], PH, vH[2], vH[3]);
                mmab(oacc[2 * dp],     PH, vL[0], vL[1]);
                mmab(oacc[2 * dp + 1], PH, vL[2], vL[3]);
                mmab(oacc[2 * dp],     PL, vH[0], vH[1]);
                mmab(oacc[2 * dp + 1], PL, vH[2], vH[3]);
            }
        }
    }

    __syncthreads();   // all pass-B compute done (stage-0 V regions free for staging)

    // ---- O cross-half reduction (already normalized) ----
    float* stg = (float*)(sm + OFF_OST);
    const int rlo = q0 + (lane >> 2), rhi = rlo + 8;
    if (cg == 1) {
        #pragma unroll
        for (int nt = 0; nt < 8; nt++) {
            int c = 8 * nt + 2 * (lane & 3);
            *(float2*)&stg[rlo * 64 + c] = make_float2(oacc[nt][0], oacc[nt][1]);
            *(float2*)&stg[rhi * 64 + c] = make_float2(oacc[nt][2], oacc[nt][3]);
        }
    }
    __syncthreads();
    if (cg == 0) {
        #pragma unroll
        for (int nt = 0; nt < 8; nt++) {
            int c = 8 * nt + 2 * (lane & 3);
            float2 s0 = *(const float2*)&stg[rlo * 64 + c];
            float2 s1 = *(const float2*)&stg[rhi * 64 + c];
            *(float2*)&out_o[row0 * DD + c] =
                make_float2(oacc[nt][0] + s0.x, oacc[nt][1] + s0.y);
            *(float2*)&out_o[(row0 + 8) * DD + c] =
                make_float2(oacc[nt][2] + s1.x, oacc[nt][3] + s1.y);
        }
    }
}

extern "C" void kernel_launch(void* const* d_in, const int* in_sizes, int n_in,
                              void* d_out, int out_size)
{
    const float* Q    = (const float*)d_in[0];
    const float* K    = (const float*)d_in[1];
    const float* V    = (const float*)d_in[2];
    const int*   mask = (const int*)d_in[3];

    float* out_o = (float*)d_out;                       // [B,H,S,D]
    float* out_p = out_o + (size_t)BB * HH * SS * DD;   // [B,H,S,S]

    convert_kernel<<<NELEM / 4 / 256, 256>>>(Q, K, V);

    cudaFuncSetAttribute(fa_mma_kernel,
                         cudaFuncAttributeMaxDynamicSharedMemorySize, SMEM_TOTAL);
    dim3 grid(SS / QB, HH, BB);   // (32, 16, 2) = 1024 CTAs, 2 per SM
    fa_mma_kernel<<<grid, NTHR, SMEM_TOTAL>>>(mask, out_o, out_p);
}

// round 11
// speedup vs baseline: 1.5972x; 1.2206x over previous
#include <cuda_runtime.h>
#include <cuda_fp16.h>
#include <stdint.h>

// ScaledDotProductAttention: B=2, H=16, S=2048, D=64, scale=8
#define BB 2
#define HH 16
#define SS 2048
#define DD 64
#define QB 64             // q rows per CTA
#define NC 64             // k cols per chunk
#define NCHUNK (SS / NC)  // 32
#define NTHR 256          // 8 warps: 4 q-groups x 2 col-halves
#define NELEM (BB * HH * SS * DD)

#define STRB 144                 // smem row stride bytes (ldmatrix conflict-free)
#define TILEB (64 * STRB)        // 9216 B per [64 x 64] fp16 tile
#define TILE_CHUNKS 512

#define OFF_QH 0
#define OFF_QL TILEB
#define OFF_STAGE (2 * TILEB)                 // 6 tiles: stage{0,1} x {KH,KL,VH}
#define ST_OFF(st, t) (OFF_STAGE + ((st) * 3 + (t)) * TILEB)
#define OFF_OST OFF_STAGE                     // O fp32 stage (16KB) overlays stage0
#define OFF_MSK (OFF_STAGE + 6 * TILEB)       // int[2048] -> float bias[2048]
#define OFF_L2  (OFF_MSK + SS * 4)            // float[64][2]
#define SMEM_TOTAL (OFF_L2 + 64 * 2 * 4)      // 82432 B -> 2 CTAs/SM

// pre-converted fp16 tensors (Q pre-scaled by log2(e)/8); V single-term
__device__ __half g_qh[NELEM], g_ql[NELEM];
__device__ __half g_kh[NELEM], g_kl[NELEM];
__device__ __half g_vh[NELEM];

__device__ __forceinline__ uint32_t s2u(const void* p) {
    uint32_t a;
    asm("{ .reg .u64 t; cvta.to.shared.u64 t, %1; cvt.u32.u64 %0, t; }" : "=r"(a) : "l"(p));
    return a;
}
__device__ __forceinline__ void ldsm4(uint32_t r[4], uint32_t a) {
    asm volatile("ldmatrix.sync.aligned.m8n8.x4.shared.b16 {%0,%1,%2,%3}, [%4];"
                 : "=r"(r[0]), "=r"(r[1]), "=r"(r[2]), "=r"(r[3]) : "r"(a));
}
__device__ __forceinline__ void ldsm4t(uint32_t r[4], uint32_t a) {
    asm volatile("ldmatrix.sync.aligned.m8n8.x4.trans.shared.b16 {%0,%1,%2,%3}, [%4];"
                 : "=r"(r[0]), "=r"(r[1]), "=r"(r[2]), "=r"(r[3]) : "r"(a));
}
__device__ __forceinline__ void mmah(float c[4], const uint32_t a[4], uint32_t b0, uint32_t b1) {
    asm volatile("mma.sync.aligned.m16n8k16.row.col.f32.f16.f16.f32 "
                 "{%0,%1,%2,%3}, {%4,%5,%6,%7}, {%8,%9}, {%0,%1,%2,%3};"
                 : "+f"(c[0]), "+f"(c[1]), "+f"(c[2]), "+f"(c[3])
                 : "r"(a[0]), "r"(a[1]), "r"(a[2]), "r"(a[3]), "r"(b0), "r"(b1));
}
__device__ __forceinline__ uint32_t pkh(float a, float b) {
    __half2 t = __floats2half2_rn(a, b);
    return *(uint32_t*)&t;
}
__device__ __forceinline__ float ex2(float x) {
    float r;
    asm("ex2.approx.f32 %0, %1;" : "=f"(r) : "f"(x));
    return r;
}
#define CPA16(dst, src) \
    asm volatile("cp.async.cg.shared.global [%0], [%1], 16;" :: "r"(dst), "l"(src) : "memory")
#define CPA_COMMIT() asm volatile("cp.async.commit_group;" ::: "memory")
#define CPA_WAIT0()  asm volatile("cp.async.wait_group 0;" ::: "memory")

// ---- pre-pass: fp32 -> fp16 hi/lo split (V: hi only) ----
__device__ __forceinline__ void split4h(float4 x, uint2& hi, uint2& lo) {
    float h0 = __half2float(__float2half_rn(x.x));
    float h1 = __half2float(__float2half_rn(x.y));
    float h2 = __half2float(__float2half_rn(x.z));
    float h3 = __half2float(__float2half_rn(x.w));
    hi = make_uint2(pkh(h0, h1), pkh(h2, h3));
    lo = make_uint2(pkh(x.x - h0, x.y - h1), pkh(x.z - h2, x.w - h3));
}
__global__ void convert_kernel(const float* __restrict__ Q, const float* __restrict__ K,
                               const float* __restrict__ V)
{
    long i = (long)blockIdx.x * blockDim.x + threadIdx.x;
    if (i >= NELEM / 4) return;
    long e = i * 4;
    uint2 hi, lo;
    const float QSC = 0.125f * 1.4426950408889634f;   // (1/8)*log2(e): exp -> exp2
    float4 q = *(const float4*)&Q[e];
    q.x *= QSC; q.y *= QSC; q.z *= QSC; q.w *= QSC;
    split4h(q, hi, lo);
    *(uint2*)&g_qh[e] = hi; *(uint2*)&g_ql[e] = lo;
    split4h(*(const float4*)&K[e], hi, lo);
    *(uint2*)&g_kh[e] = hi; *(uint2*)&g_kl[e] = lo;
    float4 v = *(const float4*)&V[e];
    *(uint2*)&g_vh[e] = make_uint2(pkh(v.x, v.y), pkh(v.z, v.w));
}

// cp.async a [64 x 64] fp16 tile into stride-144 smem
__device__ __forceinline__ void cpa_tile(uint32_t dstbase, const __half* src, int tid) {
    #pragma unroll
    for (int i = tid; i < TILE_CHUNKS; i += NTHR) {
        int r = i >> 3, c8 = i & 7;
        CPA16(dstbase + r * STRB + c8 * 16, src + (long)r * DD + c8 * 8);
    }
}

__global__ __launch_bounds__(NTHR, 2)
void fa_mma_kernel(const int* __restrict__ mask,
                   float* __restrict__ out_o, float* __restrict__ out_p)
{
    extern __shared__ char sm[];
    const uint32_t sb = s2u(sm);
    const int tid = threadIdx.x, wid = tid >> 5, lane = tid & 31;
    const int qg = wid & 3, cg = wid >> 2;
    const int q0 = qg * 16;

    const int qtile = blockIdx.x, h = blockIdx.y, b = blockIdx.z;
    const long bh = (long)(b * HH + h);
    const long qbase = bh * SS + (long)qtile * QB;
    const long kvbase = bh * SS;

    // ---- prologue: Q tiles + mask + KH chunk 0 ----
    cpa_tile(sb + OFF_QH, g_qh + qbase * DD, tid);
    cpa_tile(sb + OFF_QL, g_ql + qbase * DD, tid);
    #pragma unroll
    for (int i = tid; i < 512; i += NTHR)
        CPA16(sb + OFF_MSK + i * 16, mask + (long)b * SS + i * 4);
    cpa_tile(sb + ST_OFF(0, 0), g_kh + kvbase * DD, tid);
    CPA_COMMIT();

    const uint32_t kvrow = (uint32_t)cg * 32 * STRB;
    const uint32_t aoff = (uint32_t)(q0 + (lane & 15)) * STRB + ((lane >> 4) & 1) * 16;
    const uint32_t koff = kvrow + (uint32_t)((lane & 7) + ((lane & 16) ? 8 : 0)) * STRB
                        + ((lane & 8) ? 16 : 0);
    const uint32_t voff = kvrow + (uint32_t)(lane & 15) * STRB + ((lane >> 4) & 1) * 16;

    float* fbias = (float*)(sm + OFF_MSK);

    CPA_WAIT0();
    __syncthreads();

    // mask int -> float bias in place (0 pass, -1e30 masked)
    {
        int* mi = (int*)(sm + OFF_MSK);
        for (int i = tid; i < SS; i += NTHR) {
            int v = mi[i];
            fbias[i] = v ? 0.0f : -1e30f;
        }
    }
    // hoist Q fragments (m16 x k64, hi+lo = 32 regs)
    uint32_t aHq[4][4], aLq[4][4];
    #pragma unroll
    for (int s = 0; s < 4; s++) {
        ldsm4(aHq[s], sb + OFF_QH + aoff + s * 32);
        ldsm4(aLq[s], sb + OFF_QL + aoff + s * 32);
    }
    __syncthreads();   // bias visible to all

    // ================= Pass A: 1-term fp16 scores -> row sums only =================
    float rs0 = 0.0f, rs1 = 0.0f;
    for (int ch = 0; ch < NCHUNK; ch++) {
        const int st = ch & 1;
        if (ch > 0) { CPA_WAIT0(); __syncthreads(); }
        if (ch + 1 < NCHUNK) {
            cpa_tile(sb + ST_OFF(st ^ 1, 0),
                     g_kh + (kvbase + (long)(ch + 1) * NC) * DD, tid);
            CPA_COMMIT();
        }

        float acc[4][4];
        #pragma unroll
        for (int j = 0; j < 4; j++)
            #pragma unroll
            for (int i = 0; i < 4; i++) acc[j][i] = 0.0f;
        #pragma unroll
        for (int s = 0; s < 4; s++) {
            #pragma unroll
            for (int jp = 0; jp < 2; jp++) {
                uint32_t bH[4];
                ldsm4(bH, sb + ST_OFF(st, 0) + koff + jp * (16 * STRB) + s * 32);
                mmah(acc[2 * jp],     aHq[s], bH[0], bH[1]);
                mmah(acc[2 * jp + 1], aHq[s], bH[2], bH[3]);
            }
        }
        #pragma unroll
        for (int jt = 0; jt < 4; jt++) {
            int colb = ch * NC + cg * 32 + 8 * jt + 2 * (lane & 3);
            float2 fb = *(const float2*)&fbias[colb];
            rs0 += ex2(acc[jt][0] + fb.x) + ex2(acc[jt][1] + fb.y);
            rs1 += ex2(acc[jt][2] + fb.x) + ex2(acc[jt][3] + fb.y);
        }
    }

    __syncthreads();   // all warps done with A stages

    // prefetch pass-B chunk 0 (KH,KL,VH) — overlaps rowsum reduction
    cpa_tile(sb + ST_OFF(0, 0), g_kh + kvbase * DD, tid);
    cpa_tile(sb + ST_OFF(0, 1), g_kl + kvbase * DD, tid);
    cpa_tile(sb + ST_OFF(0, 2), g_vh + kvbase * DD, tid);
    CPA_COMMIT();

    // ---- row sums: quad-lane reduce, cross-half via smem ----
    rs0 += __shfl_xor_sync(0xffffffffu, rs0, 1);
    rs0 += __shfl_xor_sync(0xffffffffu, rs0, 2);
    rs1 += __shfl_xor_sync(0xffffffffu, rs1, 1);
    rs1 += __shfl_xor_sync(0xffffffffu, rs1, 2);
    float* l2p = (float*)(sm + OFF_L2);
    if ((lane & 3) == 0) {
        l2p[2 * (q0 + (lane >> 2)) + cg]     = rs0;
        l2p[2 * (q0 + 8 + (lane >> 2)) + cg] = rs1;
    }
    __syncthreads();
    const float il0 = 1.0f / (l2p[2 * (q0 + (lane >> 2))] + l2p[2 * (q0 + (lane >> 2)) + 1]);
    const float il1 = 1.0f / (l2p[2 * (q0 + 8 + (lane >> 2))] + l2p[2 * (q0 + 8 + (lane >> 2)) + 1]);
    const long row0 = qbase + q0 + (lane >> 2);

    float oacc[8][4];
    #pragma unroll
    for (int j = 0; j < 8; j++)
        #pragma unroll
        for (int i = 0; i < 4; i++) oacc[j][i] = 0.0f;

    // ========== Pass B: 3-term fp16 S -> probs out + PV (P hi/lo x Vh) ==========
    for (int ch = 0; ch < NCHUNK; ch++) {
        const int st = ch & 1;
        CPA_WAIT0();
        __syncthreads();
        if (ch + 1 < NCHUNK) {
            const long nb = (kvbase + (long)(ch + 1) * NC) * DD;
            const int ns = st ^ 1;
            cpa_tile(sb + ST_OFF(ns, 0), g_kh + nb, tid);
            cpa_tile(sb + ST_OFF(ns, 1), g_kl + nb, tid);
            cpa_tile(sb + ST_OFF(ns, 2), g_vh + nb, tid);
            CPA_COMMIT();
        }

        // 3-term fp16 S
        float acc[4][4];
        #pragma unroll
        for (int j = 0; j < 4; j++)
            #pragma unroll
            for (int i = 0; i < 4; i++) acc[j][i] = 0.0f;
        #pragma unroll
        for (int s = 0; s < 4; s++) {
            #pragma unroll
            for (int jp = 0; jp < 2; jp++) {
                uint32_t bH[4], bL[4];
                ldsm4(bH, sb + ST_OFF(st, 0) + koff + jp * (16 * STRB) + s * 32);
                ldsm4(bL, sb + ST_OFF(st, 1) + koff + jp * (16 * STRB) + s * 32);
                mmah(acc[2 * jp],     aHq[s], bH[0], bH[1]);
                mmah(acc[2 * jp + 1], aHq[s], bH[2], bH[3]);
                mmah(acc[2 * jp],     aHq[s], bL[0], bL[1]);
                mmah(acc[2 * jp + 1], aHq[s], bL[2], bL[3]);
                mmah(acc[2 * jp],     aLq[s], bH[0], bH[1]);
                mmah(acc[2 * jp + 1], aLq[s], bH[2], bH[3]);
            }
        }

        const uint32_t vh = sb + ST_OFF(st, 2) + voff;
        #pragma unroll
        for (int s2 = 0; s2 < 2; s2++) {
            uint32_t PH[4], PL[4];
            #pragma unroll
            for (int hf = 0; hf < 2; hf++) {
                const int jt = 2 * s2 + hf;
                int colb = ch * NC + cg * 32 + 8 * jt + 2 * (lane & 3);
                float2 fb = *(const float2*)&fbias[colb];
                float e0 = ex2(acc[jt][0] + fb.x);
                float e1 = ex2(acc[jt][1] + fb.y);
                float e2 = ex2(acc[jt][2] + fb.x);
                float e3 = ex2(acc[jt][3] + fb.y);
                // normalized probs out (fire-and-forget STG)
                *(float2*)&out_p[row0 * SS + colb]       = make_float2(e0 * il0, e1 * il0);
                *(float2*)&out_p[(row0 + 8) * SS + colb] = make_float2(e2 * il1, e3 * il1);
                // P hi/lo fp16 (unnormalized; O scaled by il at the end)
                float h0 = __half2float(__float2half_rn(e0));
                float h1 = __half2float(__float2half_rn(e1));
                float h2 = __half2float(__float2half_rn(e2));
                float h3 = __half2float(__float2half_rn(e3));
                PH[2 * hf]     = pkh(h0, h1);
                PH[2 * hf + 1] = pkh(h2, h3);
                PL[2 * hf]     = pkh(e0 - h0, e1 - h1);
                PL[2 * hf + 1] = pkh(e2 - h2, e3 - h3);
            }
            #pragma unroll
            for (int dp = 0; dp < 4; dp++) {
                uint32_t vH[4];
                ldsm4t(vH, vh + s2 * (16 * STRB) + dp * 32);
                mmah(oacc[2 * dp],     PH, vH[0], vH[1]);
                mmah(oacc[2 * dp + 1], PH, vH[2], vH[3]);
                mmah(oacc[2 * dp],     PL, vH[0], vH[1]);
                mmah(oacc[2 * dp + 1], PL, vH[2], vH[3]);
            }
        }
    }

    __syncthreads();   // all pass-B compute done (stage0 region free for staging)

    // ---- O cross-half reduction, normalize at write ----
    float* stg = (float*)(sm + OFF_OST);
    const int rlo = q0 + (lane >> 2), rhi = rlo + 8;
    if (cg == 1) {
        #pragma unroll
        for (int nt = 0; nt < 8; nt++) {
            int c = 8 * nt + 2 * (lane & 3);
            *(float2*)&stg[rlo * 64 + c] = make_float2(oacc[nt][0], oacc[nt][1]);
            *(float2*)&stg[rhi * 64 + c] = make_float2(oacc[nt][2], oacc[nt][3]);
        }
    }
    __syncthreads();
    if (cg == 0) {
        #pragma unroll
        for (int nt = 0; nt < 8; nt++) {
            int c = 8 * nt + 2 * (lane & 3);
            float2 s0 = *(const float2*)&stg[rlo * 64 + c];
            float2 s1 = *(const float2*)&stg[rhi * 64 + c];
            *(float2*)&out_o[row0 * DD + c] =
                make_float2((oacc[nt][0] + s0.x) * il0, (oacc[nt][1] + s0.y) * il0);
            *(float2*)&out_o[(row0 + 8) * DD + c] =
                make_float2((oacc[nt][2] + s1.x) * il1, (oacc[nt][3] + s1.y) * il1);
        }
    }
}

extern "C" void kernel_launch(void* const* d_in, const int* in_sizes, int n_in,
                              void* d_out, int out_size)
{
    const float* Q    = (const float*)d_in[0];
    const float* K    = (const float*)d_in[1];
    const float* V    = (const float*)d_in[2];
    const int*   mask = (const int*)d_in[3];

    float* out_o = (float*)d_out;                       // [B,H,S,D]
    float* out_p = out_o + (size_t)BB * HH * SS * DD;   // [B,H,S,S]

    convert_kernel<<<NELEM / 4 / 256, 256>>>(Q, K, V);

    cudaFuncSetAttribute(fa_mma_kernel,
                         cudaFuncAttributeMaxDynamicSharedMemorySize, SMEM_TOTAL);
    dim3 grid(SS / QB, HH, BB);   // (32, 16, 2) = 1024 CTAs, 2 per SM
    fa_mma_kernel<<<grid, NTHR, SMEM_TOTAL>>>(mask, out_o, out_p);
}

// round 12
// speedup vs baseline: 2.1634x; 1.3545x over previous
#include <cuda_runtime.h>
#include <cuda_fp16.h>
#include <stdint.h>

// ScaledDotProductAttention: B=2, H=16, S=2048, D=64, scale=8
#define BB 2
#define HH 16
#define SS 2048
#define DD 64
#define QB 64              // q rows per CTA
#define NCB 64             // k cols per B chunk
#define NCHB (SS / NCB)    // 32
#define NCA 128            // k cols per A chunk
#define NCHA (SS / NCA)    // 16
#define NTHR 256           // 8 warps: 4 q-groups x 2 col-halves
#define NELEM (BB * HH * SS * DD)

#define STRB 144                 // smem row stride bytes (ldmatrix conflict-free)
#define TILEB (64 * STRB)        // 9216 B per [64 x 64] fp16 tile

#define OFF_QH 0
#define OFF_QL TILEB
#define OFF_STAGE (2 * TILEB)
// B stages: st{0,1} x {KH,VH} (4 tiles). A stages: st*2*TILEB (128-row KH, 2 tiles each).
#define STB_OFF(st, t) (OFF_STAGE + ((st) * 2 + (t)) * TILEB)
#define STA_OFF(st)    (OFF_STAGE + (st) * 2 * TILEB)
#define OFF_OST OFF_STAGE                     // O fp32 stage (16KB) overlays stage region
#define OFF_MSK (OFF_STAGE + 4 * TILEB)       // int[2048] -> float bias[2048]
#define OFF_L2  (OFF_MSK + SS * 4)            // float[64][2]
#define SMEM_TOTAL (OFF_L2 + 64 * 2 * 4)      // 64000 B -> 2 CTAs/SM

// pre-converted fp16 tensors (Q pre-scaled by log2(e)/8); K,V single-term, Q hi/lo
__device__ __half g_qh[NELEM], g_ql[NELEM];
__device__ __half g_kh[NELEM];
__device__ __half g_vh[NELEM];

__device__ __forceinline__ uint32_t s2u(const void* p) {
    uint32_t a;
    asm("{ .reg .u64 t; cvta.to.shared.u64 t, %1; cvt.u32.u64 %0, t; }" : "=r"(a) : "l"(p));
    return a;
}
__device__ __forceinline__ void ldsm4(uint32_t r[4], uint32_t a) {
    asm volatile("ldmatrix.sync.aligned.m8n8.x4.shared.b16 {%0,%1,%2,%3}, [%4];"
                 : "=r"(r[0]), "=r"(r[1]), "=r"(r[2]), "=r"(r[3]) : "r"(a));
}
__device__ __forceinline__ void ldsm4t(uint32_t r[4], uint32_t a) {
    asm volatile("ldmatrix.sync.aligned.m8n8.x4.trans.shared.b16 {%0,%1,%2,%3}, [%4];"
                 : "=r"(r[0]), "=r"(r[1]), "=r"(r[2]), "=r"(r[3]) : "r"(a));
}
__device__ __forceinline__ void mmah(float c[4], const uint32_t a[4], uint32_t b0, uint32_t b1) {
    asm volatile("mma.sync.aligned.m16n8k16.row.col.f32.f16.f16.f32 "
                 "{%0,%1,%2,%3}, {%4,%5,%6,%7}, {%8,%9}, {%0,%1,%2,%3};"
                 : "+f"(c[0]), "+f"(c[1]), "+f"(c[2]), "+f"(c[3])
                 : "r"(a[0]), "r"(a[1]), "r"(a[2]), "r"(a[3]), "r"(b0), "r"(b1));
}
__device__ __forceinline__ uint32_t pkh(float a, float b) {
    __half2 t = __floats2half2_rn(a, b);
    return *(uint32_t*)&t;
}
__device__ __forceinline__ float ex2(float x) {
    float r;
    asm("ex2.approx.f32 %0, %1;" : "=f"(r) : "f"(x));
    return r;
}
#define CPA16(dst, src) \
    asm volatile("cp.async.cg.shared.global [%0], [%1], 16;" :: "r"(dst), "l"(src) : "memory")
#define CPA_COMMIT() asm volatile("cp.async.commit_group;" ::: "memory")
#define CPA_WAIT0()  asm volatile("cp.async.wait_group 0;" ::: "memory")

// ---- pre-pass: Q -> fp16 hi/lo (scaled), K/V -> fp16 ----
__global__ void convert_kernel(const float* __restrict__ Q, const float* __restrict__ K,
                               const float* __restrict__ V)
{
    long i = (long)blockIdx.x * blockDim.x + threadIdx.x;
    if (i >= NELEM / 4) return;
    long e = i * 4;
    const float QSC = 0.125f * 1.4426950408889634f;   // (1/8)*log2(e): exp -> exp2
    float4 q = *(const float4*)&Q[e];
    q.x *= QSC; q.y *= QSC; q.z *= QSC; q.w *= QSC;
    float h0 = __half2float(__float2half_rn(q.x));
    float h1 = __half2float(__float2half_rn(q.y));
    float h2 = __half2float(__float2half_rn(q.z));
    float h3 = __half2float(__float2half_rn(q.w));
    *(uint2*)&g_qh[e] = make_uint2(pkh(h0, h1), pkh(h2, h3));
    *(uint2*)&g_ql[e] = make_uint2(pkh(q.x - h0, q.y - h1), pkh(q.z - h2, q.w - h3));
    float4 k = *(const float4*)&K[e];
    *(uint2*)&g_kh[e] = make_uint2(pkh(k.x, k.y), pkh(k.z, k.w));
    float4 v = *(const float4*)&V[e];
    *(uint2*)&g_vh[e] = make_uint2(pkh(v.x, v.y), pkh(v.z, v.w));
}

// cp.async [rows x 64] fp16 tile into stride-144 smem
__device__ __forceinline__ void cpa_tile64(uint32_t dstbase, const __half* src, int tid) {
    #pragma unroll
    for (int i = tid; i < 512; i += NTHR) {
        int r = i >> 3, c8 = i & 7;
        CPA16(dstbase + r * STRB + c8 * 16, src + (long)r * DD + c8 * 8);
    }
}
__device__ __forceinline__ void cpa_tile128(uint32_t dstbase, const __half* src, int tid) {
    #pragma unroll
    for (int i = tid; i < 1024; i += NTHR) {
        int r = i >> 3, c8 = i & 7;
        CPA16(dstbase + r * STRB + c8 * 16, src + (long)r * DD + c8 * 8);
    }
}

__global__ __launch_bounds__(NTHR, 2)
void fa_mma_kernel(const int* __restrict__ mask,
                   float* __restrict__ out_o, float* __restrict__ out_p)
{
    extern __shared__ char sm[];
    const uint32_t sb = s2u(sm);
    const int tid = threadIdx.x, wid = tid >> 5, lane = tid & 31;
    const int qg = wid & 3, cg = wid >> 2;
    const int q0 = qg * 16;

    const int qtile = blockIdx.x, h = blockIdx.y, b = blockIdx.z;
    const long bh = (long)(b * HH + h);
    const long qbase = bh * SS + (long)qtile * QB;
    const long kvbase = bh * SS;

    // ---- prologue: Q tiles + mask + A chunk 0 (128-row KH) ----
    cpa_tile64(sb + OFF_QH, g_qh + qbase * DD, tid);
    cpa_tile64(sb + OFF_QL, g_ql + qbase * DD, tid);
    #pragma unroll
    for (int i = tid; i < 512; i += NTHR)
        CPA16(sb + OFF_MSK + i * 16, mask + (long)b * SS + i * 4);
    cpa_tile128(sb + STA_OFF(0), g_kh + kvbase * DD, tid);
    CPA_COMMIT();

    // per-lane ldmatrix addresses
    const uint32_t aoff = (uint32_t)(q0 + (lane & 15)) * STRB + ((lane >> 4) & 1) * 16;
    const uint32_t koffA = (uint32_t)(cg * 64 + (lane & 7) + ((lane & 16) ? 8 : 0)) * STRB
                         + ((lane & 8) ? 16 : 0);
    const uint32_t koffB = (uint32_t)(cg * 32 + (lane & 7) + ((lane & 16) ? 8 : 0)) * STRB
                         + ((lane & 8) ? 16 : 0);
    const uint32_t voff = (uint32_t)(cg * 32 + (lane & 15)) * STRB + ((lane >> 4) & 1) * 16;

    float* fbias = (float*)(sm + OFF_MSK);

    CPA_WAIT0();
    __syncthreads();

    // mask int -> float bias in place (0 pass, -1e30 masked)
    {
        int* mi = (int*)(sm + OFF_MSK);
        for (int i = tid; i < SS; i += NTHR) {
            int v = mi[i];
            fbias[i] = v ? 0.0f : -1e30f;
        }
    }
    // hoist Q fragments (m16 x k64, hi+lo = 32 regs)
    uint32_t aHq[4][4], aLq[4][4];
    #pragma unroll
    for (int s = 0; s < 4; s++) {
        ldsm4(aHq[s], sb + OFF_QH + aoff + s * 32);
        ldsm4(aLq[s], sb + OFF_QL + aoff + s * 32);
    }
    __syncthreads();   // bias visible to all

    // ========= Pass A: 1-term fp16 scores over 128-col chunks -> row sums =========
    float rs0 = 0.0f, rs1 = 0.0f;
    for (int ch = 0; ch < NCHA; ch++) {
        const int st = ch & 1;
        if (ch > 0) { CPA_WAIT0(); __syncthreads(); }
        if (ch + 1 < NCHA) {
            cpa_tile128(sb + STA_OFF(st ^ 1),
                        g_kh + (kvbase + (long)(ch + 1) * NCA) * DD, tid);
            CPA_COMMIT();
        }

        float acc[8][4];
        #pragma unroll
        for (int j = 0; j < 8; j++)
            #pragma unroll
            for (int i = 0; i < 4; i++) acc[j][i] = 0.0f;
        #pragma unroll
        for (int s = 0; s < 4; s++) {
            #pragma unroll
            for (int jp = 0; jp < 4; jp++) {
                uint32_t bH[4];
                ldsm4(bH, sb + STA_OFF(st) + koffA + jp * (16 * STRB) + s * 32);
                mmah(acc[2 * jp],     aHq[s], bH[0], bH[1]);
                mmah(acc[2 * jp + 1], aHq[s], bH[2], bH[3]);
            }
        }
        #pragma unroll
        for (int jt = 0; jt < 8; jt++) {
            int colb = ch * NCA + cg * 64 + 8 * jt + 2 * (lane & 3);
            float2 fb = *(const float2*)&fbias[colb];
            rs0 += ex2(acc[jt][0] + fb.x) + ex2(acc[jt][1] + fb.y);
            rs1 += ex2(acc[jt][2] + fb.x) + ex2(acc[jt][3] + fb.y);
        }
    }

    __syncthreads();   // all warps done with A stages

    // prefetch pass-B chunk 0 (KH, VH) — overlaps rowsum reduction
    cpa_tile64(sb + STB_OFF(0, 0), g_kh + kvbase * DD, tid);
    cpa_tile64(sb + STB_OFF(0, 1), g_vh + kvbase * DD, tid);
    CPA_COMMIT();

    // ---- row sums: quad-lane reduce, cross-half via smem ----
    rs0 += __shfl_xor_sync(0xffffffffu, rs0, 1);
    rs0 += __shfl_xor_sync(0xffffffffu, rs0, 2);
    rs1 += __shfl_xor_sync(0xffffffffu, rs1, 1);
    rs1 += __shfl_xor_sync(0xffffffffu, rs1, 2);
    float* l2p = (float*)(sm + OFF_L2);
    if ((lane & 3) == 0) {
        l2p[2 * (q0 + (lane >> 2)) + cg]     = rs0;
        l2p[2 * (q0 + 8 + (lane >> 2)) + cg] = rs1;
    }
    __syncthreads();
    const float il0 = 1.0f / (l2p[2 * (q0 + (lane >> 2))] + l2p[2 * (q0 + (lane >> 2)) + 1]);
    const float il1 = 1.0f / (l2p[2 * (q0 + 8 + (lane >> 2))] + l2p[2 * (q0 + 8 + (lane >> 2)) + 1]);
    const long row0 = qbase + q0 + (lane >> 2);

    float oacc[8][4];
    #pragma unroll
    for (int j = 0; j < 8; j++)
        #pragma unroll
        for (int i = 0; i < 4; i++) oacc[j][i] = 0.0f;

    // ===== Pass B: 2-term S (qh+ql)·kh -> probs out + PV (P_hi x V_hi) =====
    for (int ch = 0; ch < NCHB; ch++) {
        const int st = ch & 1;
        CPA_WAIT0();
        __syncthreads();
        if (ch + 1 < NCHB) {
            const long nb = (kvbase + (long)(ch + 1) * NCB) * DD;
            const int ns = st ^ 1;
            cpa_tile64(sb + STB_OFF(ns, 0), g_kh + nb, tid);
            cpa_tile64(sb + STB_OFF(ns, 1), g_vh + nb, tid);
            CPA_COMMIT();
        }

        // 2-term S
        float acc[4][4];
        #pragma unroll
        for (int j = 0; j < 4; j++)
            #pragma unroll
            for (int i = 0; i < 4; i++) acc[j][i] = 0.0f;
        #pragma unroll
        for (int s = 0; s < 4; s++) {
            #pragma unroll
            for (int jp = 0; jp < 2; jp++) {
                uint32_t bH[4];
                ldsm4(bH, sb + STB_OFF(st, 0) + koffB + jp * (16 * STRB) + s * 32);
                mmah(acc[2 * jp],     aHq[s], bH[0], bH[1]);
                mmah(acc[2 * jp + 1], aHq[s], bH[2], bH[3]);
                mmah(acc[2 * jp],     aLq[s], bH[0], bH[1]);
                mmah(acc[2 * jp + 1], aLq[s], bH[2], bH[3]);
            }
        }

        const uint32_t vh = sb + STB_OFF(st, 1) + voff;
        #pragma unroll
        for (int s2 = 0; s2 < 2; s2++) {
            uint32_t PH[4];
            #pragma unroll
            for (int hf = 0; hf < 2; hf++) {
                const int jt = 2 * s2 + hf;
                int colb = ch * NCB + cg * 32 + 8 * jt + 2 * (lane & 3);
                float2 fb = *(const float2*)&fbias[colb];
                float e0 = ex2(acc[jt][0] + fb.x);
                float e1 = ex2(acc[jt][1] + fb.y);
                float e2 = ex2(acc[jt][2] + fb.x);
                float e3 = ex2(acc[jt][3] + fb.y);
                // normalized probs out (fire-and-forget STG)
                *(float2*)&out_p[row0 * SS + colb]       = make_float2(e0 * il0, e1 * il0);
                *(float2*)&out_p[(row0 + 8) * SS + colb] = make_float2(e2 * il1, e3 * il1);
                PH[2 * hf]     = pkh(e0, e1);
                PH[2 * hf + 1] = pkh(e2, e3);
            }
            #pragma unroll
            for (int dp = 0; dp < 4; dp++) {
                uint32_t vH[4];
                ldsm4t(vH, vh + s2 * (16 * STRB) + dp * 32);
                mmah(oacc[2 * dp],     PH, vH[0], vH[1]);
                mmah(oacc[2 * dp + 1], PH, vH[2], vH[3]);
            }
        }
    }

    __syncthreads();   // all pass-B compute done (stage region free for staging)

    // ---- O cross-half reduction, normalize at write ----
    float* stg = (float*)(sm + OFF_OST);
    const int rlo = q0 + (lane >> 2), rhi = rlo + 8;
    if (cg == 1) {
        #pragma unroll
        for (int nt = 0; nt < 8; nt++) {
            int c = 8 * nt + 2 * (lane & 3);
            *(float2*)&stg[rlo * 64 + c] = make_float2(oacc[nt][0], oacc[nt][1]);
            *(float2*)&stg[rhi * 64 + c] = make_float2(oacc[nt][2], oacc[nt][3]);
        }
    }
    __syncthreads();
    if (cg == 0) {
        #pragma unroll
        for (int nt = 0; nt < 8; nt++) {
            int c = 8 * nt + 2 * (lane & 3);
            float2 s0 = *(const float2*)&stg[rlo * 64 + c];
            float2 s1 = *(const float2*)&stg[rhi * 64 + c];
            *(float2*)&out_o[row0 * DD + c] =
                make_float2((oacc[nt][0] + s0.x) * il0, (oacc[nt][1] + s0.y) * il0);
            *(float2*)&out_o[(row0 + 8) * DD + c] =
                make_float2((oacc[nt][2] + s1.x) * il1, (oacc[nt][3] + s1.y) * il1);
        }
    }
}

extern "C" void kernel_launch(void* const* d_in, const int* in_sizes, int n_in,
                              void* d_out, int out_size)
{
    const float* Q    = (const float*)d_in[0];
    const float* K    = (const float*)d_in[1];
    const float* V    = (const float*)d_in[2];
    const int*   mask = (const int*)d_in[3];

    float* out_o = (float*)d_out;                       // [B,H,S,D]
    float* out_p = out_o + (size_t)BB * HH * SS * DD;   // [B,H,S,S]

    convert_kernel<<<NELEM / 4 / 256, 256>>>(Q, K, V);

    cudaFuncSetAttribute(fa_mma_kernel,
                         cudaFuncAttributeMaxDynamicSharedMemorySize, SMEM_TOTAL);
    dim3 grid(SS / QB, HH, BB);   // (32, 16, 2) = 1024 CTAs, 2 per SM
    fa_mma_kernel<<<grid, NTHR, SMEM_TOTAL>>>(mask, out_o, out_p);
}